// round 1
// baseline (speedup 1.0000x reference)
#include <cuda_runtime.h>

#define FULL_MASK 0xffffffffu

// Scratch for tree_v, laid out as [B=16][D=256] (head h occupies channels h*32..h*32+31)
__device__ float g_tv[16 * 256];

// ---------------------------------------------------------------------------
// Kernel A: LIF tree. One warp per (b, h). Lane = channel within head (hd=32).
// xk[m]/xv[m] hold element [node m][lane]. Matmul ok_o = sum_d xk_d * W[n,o,d]
// done with shuffle-broadcast of xk_d across the warp (lane = o).
// ---------------------------------------------------------------------------
template <int N>
__device__ __forceinline__ void level_step(
    float* xk, float* xv, int base, int lane,
    const float* __restrict__ W, const float* __restrict__ bvec,
    const float* __restrict__ thr, const float* __restrict__ tau,
    const float* __restrict__ vres)
{
#pragma unroll
    for (int l = 0; l < N; ++l) {
        const int node = base + l;
        const float* Wrow = W + node * 1024 + lane * 32;  // W[node][o=lane][d]
        float ok = 0.f, ov = 0.f;
#pragma unroll
        for (int d = 0; d < 32; ++d) {
            const float ak = __shfl_sync(FULL_MASK, xk[l], d);
            const float av = __shfl_sync(FULL_MASK, xv[l], d);
            const float w  = Wrow[d];
            ok = fmaf(ak, w, ok);
            ov = fmaf(av, w, ov);
        }
        const float bl = bvec[node * 32 + lane];
        ok += bl;
        ov += bl;

        // LIF pair on the *inputs* (elementwise per channel = per lane)
        const float th = thr[node * 32 + lane];
        const float ta = tau[node * 32 + lane];
        const float vr = vres[node * 32 + lane];
        const float sk = (xk[l] >= th) ? 1.f : 0.f;
        const float va = xk[l] * (1.f - sk) + vr * sk;
        const float v2 = fmaf(ta, va, xv[l]);
        const float sv = (v2 >= th) ? 1.f : 0.f;

        xk[l] = ok * sk;
        xv[l] = ov * sv;
    }
}

__global__ void tree_kernel(const float* __restrict__ key_value,
                            const float* __restrict__ W,
                            const float* __restrict__ bvec,
                            const float* __restrict__ thr,
                            const float* __restrict__ tau,
                            const float* __restrict__ vres)
{
    const int wid  = (blockIdx.x * blockDim.x + threadIdx.x) >> 5;
    const int lane = threadIdx.x & 31;
    if (wid >= 16 * 8) return;
    const int b = wid >> 3;   // batch
    const int h = wid & 7;    // head

    // leaf[b,h,m,:] = key_value[b, m, h*32 + :], m = 0..7
    float xk[8], xv[8];
#pragma unroll
    for (int m = 0; m < 8; ++m) {
        const float v = key_value[(b * 16 + m) * 256 + h * 32 + lane];
        xk[m] = v;
        xv[m] = v;
    }

    // level nodes 7..14 (n=8)
    level_step<8>(xk, xv, 7, lane, W, bvec, thr, tau, vres);
    // merge 8->4, level nodes 3..6
#pragma unroll
    for (int l = 0; l < 4; ++l) {
        xk[l] = 0.5f * (xk[2 * l] + xk[2 * l + 1]);
        xv[l] = 0.5f * (xv[2 * l] + xv[2 * l + 1]);
    }
    level_step<4>(xk, xv, 3, lane, W, bvec, thr, tau, vres);
    // merge 4->2, level nodes 1..2
#pragma unroll
    for (int l = 0; l < 2; ++l) {
        xk[l] = 0.5f * (xk[2 * l] + xk[2 * l + 1]);
        xv[l] = 0.5f * (xv[2 * l] + xv[2 * l + 1]);
    }
    level_step<2>(xk, xv, 1, lane, W, bvec, thr, tau, vres);
    // merge 2->1, level node 0
    xk[0] = 0.5f * (xk[0] + xk[1]);
    xv[0] = 0.5f * (xv[0] + xv[1]);
    level_step<1>(xk, xv, 0, lane, W, bvec, thr, tau, vres);

    // softmax over a single tree node == 1.0, so attn_out = tree_v broadcast.
    g_tv[b * 256 + h * 32 + lane] = xv[0];
}

// ---------------------------------------------------------------------------
// Kernel B: fused residual-add + LayerNorm. One warp per row (D=256).
// Each lane: 2x float4 (8 floats). HBM-bound: 268 MB total traffic.
// ---------------------------------------------------------------------------
__global__ void ln_kernel(const float* __restrict__ query,
                          const float* __restrict__ gamma,
                          const float* __restrict__ beta,
                          float* __restrict__ out)
{
    const int warps_per_block = blockDim.x >> 5;
    const long long row = (long long)blockIdx.x * warps_per_block + (threadIdx.x >> 5);
    const int lane = threadIdx.x & 31;
    const int b = (int)(row >> 13);  // row / 8192

    const float4* __restrict__ qr  = reinterpret_cast<const float4*>(query) + row * 64;
    const float4* __restrict__ tvr = reinterpret_cast<const float4*>(g_tv) + b * 64;
    const float4* __restrict__ g4  = reinterpret_cast<const float4*>(gamma);
    const float4* __restrict__ be4 = reinterpret_cast<const float4*>(beta);

    const float4 q0 = __ldg(&qr[lane]);
    const float4 q1 = __ldg(&qr[lane + 32]);
    const float4 t0 = tvr[lane];
    const float4 t1 = tvr[lane + 32];

    float4 x0 = make_float4(q0.x + t0.x, q0.y + t0.y, q0.z + t0.z, q0.w + t0.w);
    float4 x1 = make_float4(q1.x + t1.x, q1.y + t1.y, q1.z + t1.z, q1.w + t1.w);

    float s  = x0.x + x0.y + x0.z + x0.w + x1.x + x1.y + x1.z + x1.w;
    float ss = x0.x * x0.x + x0.y * x0.y + x0.z * x0.z + x0.w * x0.w
             + x1.x * x1.x + x1.y * x1.y + x1.z * x1.z + x1.w * x1.w;

#pragma unroll
    for (int off = 16; off > 0; off >>= 1) {
        s  += __shfl_xor_sync(FULL_MASK, s, off);
        ss += __shfl_xor_sync(FULL_MASK, ss, off);
    }

    const float mean = s * (1.f / 256.f);
    const float var  = ss * (1.f / 256.f) - mean * mean;
    const float inv  = rsqrtf(var + 1e-5f);

    const float4 g0 = __ldg(&g4[lane]);
    const float4 g1 = __ldg(&g4[lane + 32]);
    const float4 b0 = __ldg(&be4[lane]);
    const float4 b1 = __ldg(&be4[lane + 32]);

    float4 y0, y1;
    y0.x = fmaf((x0.x - mean) * inv, g0.x, b0.x);
    y0.y = fmaf((x0.y - mean) * inv, g0.y, b0.y);
    y0.z = fmaf((x0.z - mean) * inv, g0.z, b0.z);
    y0.w = fmaf((x0.w - mean) * inv, g0.w, b0.w);
    y1.x = fmaf((x1.x - mean) * inv, g1.x, b1.x);
    y1.y = fmaf((x1.y - mean) * inv, g1.y, b1.y);
    y1.z = fmaf((x1.z - mean) * inv, g1.z, b1.z);
    y1.w = fmaf((x1.w - mean) * inv, g1.w, b1.w);

    float4* __restrict__ o4 = reinterpret_cast<float4*>(out) + row * 64;
    o4[lane]      = y0;
    o4[lane + 32] = y1;
}

// ---------------------------------------------------------------------------
// Inputs (metadata order): query, key_value, W, b, thr, tau, vres, gamma, beta
// Output: float32, 16*8192*256 elements
// ---------------------------------------------------------------------------
extern "C" void kernel_launch(void* const* d_in, const int* in_sizes, int n_in,
                              void* d_out, int out_size)
{
    (void)in_sizes; (void)n_in; (void)out_size;
    const float* query = (const float*)d_in[0];
    const float* kv    = (const float*)d_in[1];
    const float* W     = (const float*)d_in[2];
    const float* bvec  = (const float*)d_in[3];
    const float* thr   = (const float*)d_in[4];
    const float* tau   = (const float*)d_in[5];
    const float* vres  = (const float*)d_in[6];
    const float* gamma = (const float*)d_in[7];
    const float* beta  = (const float*)d_in[8];
    float* out = (float*)d_out;

    // Kernel A: 128 warps total -> 16 blocks x 256 threads (8 warps each)
    tree_kernel<<<16, 256>>>(kv, W, bvec, thr, tau, vres);

    // Kernel B: 131072 rows, 8 warps/block -> 16384 blocks
    ln_kernel<<<16384, 256>>>(query, gamma, beta, out);
}

// round 2
// speedup vs baseline: 1.9159x; 1.9159x over previous
#include <cuda_runtime.h>

#define FULL_MASK 0xffffffffu

// Scratch for tree_v, laid out as [B=16][D=256] (head h occupies channels h*32..h*32+31)
__device__ float g_tv[16 * 256];

// ---------------------------------------------------------------------------
// Kernel A: LIF tree. Grid: 64 blocks x 64 threads.
//   block -> (b = blockIdx>>2, head-pair = blockIdx&3); warp w handles head
//   h = pair*2 + w. Lane = output channel o (hd = 32).
// W for the current level is staged in shared memory with padded rows
// (stride 33 floats) so the compute reads Ws[l][lane][d] conflict-free:
// bank = (lane*33 + d) & 31 = (lane + d) & 31 -> all distinct per d.
// ---------------------------------------------------------------------------
template <int N>
__device__ __forceinline__ void load_W_level(float* __restrict__ Ws,
                                             const float* __restrict__ W,
                                             int baseNode, int tid)
{
    const float4* __restrict__ W4 = reinterpret_cast<const float4*>(W + baseNode * 1024);
#pragma unroll 4
    for (int i = tid; i < N * 256; i += 64) {
        const float4 w = W4[i];
        const int node = i >> 8;
        const int rem  = i & 255;
        const int o    = rem >> 3;
        const int d4   = (rem & 7) << 2;
        float* dst = &Ws[node * 1056 + o * 33 + d4];
        dst[0] = w.x; dst[1] = w.y; dst[2] = w.z; dst[3] = w.w;
    }
}

template <int N>
__device__ __forceinline__ void level_smem(
    float* xk, float* xv, int baseNode, int lane,
    const float* __restrict__ Ws,
    const float* __restrict__ bvec, const float* __restrict__ thr,
    const float* __restrict__ tau,  const float* __restrict__ vres)
{
#pragma unroll
    for (int l = 0; l < N; ++l) {
        const int node = baseNode + l;
        const float* __restrict__ wrow = Ws + l * 1056 + lane * 33;
        float ok = 0.f, ov = 0.f;
#pragma unroll
        for (int d = 0; d < 32; ++d) {
            const float ak = __shfl_sync(FULL_MASK, xk[l], d);
            const float av = __shfl_sync(FULL_MASK, xv[l], d);
            const float w  = wrow[d];
            ok = fmaf(ak, w, ok);
            ov = fmaf(av, w, ov);
        }
        const float bl = __ldg(&bvec[node * 32 + lane]);
        ok += bl;
        ov += bl;

        const float th = __ldg(&thr[node * 32 + lane]);
        const float ta = __ldg(&tau[node * 32 + lane]);
        const float vr = __ldg(&vres[node * 32 + lane]);
        const float sk = (xk[l] >= th) ? 1.f : 0.f;
        const float va = xk[l] * (1.f - sk) + vr * sk;
        const float v2 = fmaf(ta, va, xv[l]);
        const float sv = (v2 >= th) ? 1.f : 0.f;

        xk[l] = ok * sk;
        xv[l] = ov * sv;
    }
}

__global__ __launch_bounds__(64) void tree_kernel(
    const float* __restrict__ key_value,
    const float* __restrict__ W,
    const float* __restrict__ bvec,
    const float* __restrict__ thr,
    const float* __restrict__ tau,
    const float* __restrict__ vres)
{
    __shared__ float Ws[8 * 1056];  // 33792 B, max level (8 nodes)

    const int tid  = threadIdx.x;
    const int lane = tid & 31;
    const int wid  = tid >> 5;
    const int b    = blockIdx.x >> 2;
    const int h    = ((blockIdx.x & 3) << 1) | wid;

    // leaf[b,h,m,:] = key_value[b, m, h*32 + :], m = 0..7
    float xk[8], xv[8];
#pragma unroll
    for (int m = 0; m < 8; ++m) {
        const float v = __ldg(&key_value[(b * 16 + m) * 256 + h * 32 + lane]);
        xk[m] = v;
        xv[m] = v;
    }

    // Level 1: nodes 7..14 on 8 leaves
    load_W_level<8>(Ws, W, 7, tid);
    __syncthreads();
    level_smem<8>(xk, xv, 7, lane, Ws, bvec, thr, tau, vres);
    __syncthreads();

    // merge 8->4, level nodes 3..6
#pragma unroll
    for (int l = 0; l < 4; ++l) {
        xk[l] = 0.5f * (xk[2 * l] + xk[2 * l + 1]);
        xv[l] = 0.5f * (xv[2 * l] + xv[2 * l + 1]);
    }
    load_W_level<4>(Ws, W, 3, tid);
    __syncthreads();
    level_smem<4>(xk, xv, 3, lane, Ws, bvec, thr, tau, vres);
    __syncthreads();

    // merge 4->2, level nodes 1..2
#pragma unroll
    for (int l = 0; l < 2; ++l) {
        xk[l] = 0.5f * (xk[2 * l] + xk[2 * l + 1]);
        xv[l] = 0.5f * (xv[2 * l] + xv[2 * l + 1]);
    }
    load_W_level<2>(Ws, W, 1, tid);
    __syncthreads();
    level_smem<2>(xk, xv, 1, lane, Ws, bvec, thr, tau, vres);
    __syncthreads();

    // merge 2->1, level node 0
    xk[0] = 0.5f * (xk[0] + xk[1]);
    xv[0] = 0.5f * (xv[0] + xv[1]);
    load_W_level<1>(Ws, W, 0, tid);
    __syncthreads();
    level_smem<1>(xk, xv, 0, lane, Ws, bvec, thr, tau, vres);

    // softmax over a single tree node == 1.0 -> attn_out = tree_v broadcast.
    g_tv[b * 256 + h * 32 + lane] = xv[0];
}

// ---------------------------------------------------------------------------
// Kernel B: fused residual-add + LayerNorm. One warp per TWO rows (D=256)
// for doubled memory-level parallelism. 268 MB mandatory HBM traffic.
// ---------------------------------------------------------------------------
__global__ __launch_bounds__(256) void ln_kernel(
    const float* __restrict__ query,
    const float* __restrict__ gamma,
    const float* __restrict__ beta,
    float* __restrict__ out)
{
    const int  lane = threadIdx.x & 31;
    const long long warp = (long long)blockIdx.x * 8 + (threadIdx.x >> 5);
    const long long r0 = warp * 2;          // rows r0, r0+1 (same batch: boundary even)
    const int  b = (int)(r0 >> 13);

    const float4* __restrict__ q0r = reinterpret_cast<const float4*>(query) + r0 * 64;
    const float4* __restrict__ q1r = q0r + 64;
    const float4* __restrict__ tvr = reinterpret_cast<const float4*>(g_tv) + b * 64;
    const float4* __restrict__ g4  = reinterpret_cast<const float4*>(gamma);
    const float4* __restrict__ be4 = reinterpret_cast<const float4*>(beta);

    // 4 independent row loads in flight
    const float4 qa0 = __ldg(&q0r[lane]);
    const float4 qa1 = __ldg(&q0r[lane + 32]);
    const float4 qb0 = __ldg(&q1r[lane]);
    const float4 qb1 = __ldg(&q1r[lane + 32]);
    const float4 t0  = tvr[lane];
    const float4 t1  = tvr[lane + 32];

    float4 xa0 = make_float4(qa0.x + t0.x, qa0.y + t0.y, qa0.z + t0.z, qa0.w + t0.w);
    float4 xa1 = make_float4(qa1.x + t1.x, qa1.y + t1.y, qa1.z + t1.z, qa1.w + t1.w);
    float4 xb0 = make_float4(qb0.x + t0.x, qb0.y + t0.y, qb0.z + t0.z, qb0.w + t0.w);
    float4 xb1 = make_float4(qb1.x + t1.x, qb1.y + t1.y, qb1.z + t1.z, qb1.w + t1.w);

    float sa  = xa0.x + xa0.y + xa0.z + xa0.w + xa1.x + xa1.y + xa1.z + xa1.w;
    float ssa = xa0.x*xa0.x + xa0.y*xa0.y + xa0.z*xa0.z + xa0.w*xa0.w
              + xa1.x*xa1.x + xa1.y*xa1.y + xa1.z*xa1.z + xa1.w*xa1.w;
    float sb  = xb0.x + xb0.y + xb0.z + xb0.w + xb1.x + xb1.y + xb1.z + xb1.w;
    float ssb = xb0.x*xb0.x + xb0.y*xb0.y + xb0.z*xb0.z + xb0.w*xb0.w
              + xb1.x*xb1.x + xb1.y*xb1.y + xb1.z*xb1.z + xb1.w*xb1.w;

#pragma unroll
    for (int off = 16; off > 0; off >>= 1) {
        sa  += __shfl_xor_sync(FULL_MASK, sa,  off);
        ssa += __shfl_xor_sync(FULL_MASK, ssa, off);
        sb  += __shfl_xor_sync(FULL_MASK, sb,  off);
        ssb += __shfl_xor_sync(FULL_MASK, ssb, off);
    }

    const float ma   = sa * (1.f / 256.f);
    const float inva = rsqrtf(ssa * (1.f / 256.f) - ma * ma + 1e-5f);
    const float mb   = sb * (1.f / 256.f);
    const float invb = rsqrtf(ssb * (1.f / 256.f) - mb * mb + 1e-5f);

    const float4 g0 = __ldg(&g4[lane]);
    const float4 g1 = __ldg(&g4[lane + 32]);
    const float4 b0 = __ldg(&be4[lane]);
    const float4 b1 = __ldg(&be4[lane + 32]);

    float4 ya0, ya1, yb0, yb1;
    ya0.x = fmaf((xa0.x - ma) * inva, g0.x, b0.x);
    ya0.y = fmaf((xa0.y - ma) * inva, g0.y, b0.y);
    ya0.z = fmaf((xa0.z - ma) * inva, g0.z, b0.z);
    ya0.w = fmaf((xa0.w - ma) * inva, g0.w, b0.w);
    ya1.x = fmaf((xa1.x - ma) * inva, g1.x, b1.x);
    ya1.y = fmaf((xa1.y - ma) * inva, g1.y, b1.y);
    ya1.z = fmaf((xa1.z - ma) * inva, g1.z, b1.z);
    ya1.w = fmaf((xa1.w - ma) * inva, g1.w, b1.w);
    yb0.x = fmaf((xb0.x - mb) * invb, g0.x, b0.x);
    yb0.y = fmaf((xb0.y - mb) * invb, g0.y, b0.y);
    yb0.z = fmaf((xb0.z - mb) * invb, g0.z, b0.z);
    yb0.w = fmaf((xb0.w - mb) * invb, g0.w, b0.w);
    yb1.x = fmaf((xb1.x - mb) * invb, g1.x, b1.x);
    yb1.y = fmaf((xb1.y - mb) * invb, g1.y, b1.y);
    yb1.z = fmaf((xb1.z - mb) * invb, g1.z, b1.z);
    yb1.w = fmaf((xb1.w - mb) * invb, g1.w, b1.w);

    float4* __restrict__ o0 = reinterpret_cast<float4*>(out) + r0 * 64;
    float4* __restrict__ o1 = o0 + 64;
    o0[lane]      = ya0;
    o0[lane + 32] = ya1;
    o1[lane]      = yb0;
    o1[lane + 32] = yb1;
}

// ---------------------------------------------------------------------------
// Inputs (metadata order): query, key_value, W, b, thr, tau, vres, gamma, beta
// Output: float32, 16*8192*256 elements
// ---------------------------------------------------------------------------
extern "C" void kernel_launch(void* const* d_in, const int* in_sizes, int n_in,
                              void* d_out, int out_size)
{
    (void)in_sizes; (void)n_in; (void)out_size;
    const float* query = (const float*)d_in[0];
    const float* kv    = (const float*)d_in[1];
    const float* W     = (const float*)d_in[2];
    const float* bvec  = (const float*)d_in[3];
    const float* thr   = (const float*)d_in[4];
    const float* tau   = (const float*)d_in[5];
    const float* vres  = (const float*)d_in[6];
    const float* gamma = (const float*)d_in[7];
    const float* beta  = (const float*)d_in[8];
    float* out = (float*)d_out;

    // Kernel A: 64 blocks x 64 threads (2 warps each; one (batch, head-pair))
    tree_kernel<<<64, 64>>>(kv, W, bvec, thr, tau, vres);

    // Kernel B: 131072 rows, 2 rows/warp, 8 warps/block -> 8192 blocks
    ln_kernel<<<8192, 256>>>(query, gamma, beta, out);
}

// round 3
// speedup vs baseline: 2.1343x; 1.1140x over previous
#include <cuda_runtime.h>

#define FULL_MASK 0xffffffffu

// Scratch for tree_v, laid out as [B=16][D=256] (head h occupies channels h*32..h*32+31)
__device__ float g_tv[16 * 256];

// ---------------------------------------------------------------------------
// Kernel A: LIF tree. One block per batch (16 blocks x 256 threads).
// Warp w = head h (8 warps = 8 heads). Lane = output channel o (hd = 32).
// ALL 15 nodes' W (padded stride-33 rows -> conflict-free LDS) plus
// b/thr/tau/vres are prefetched into dynamic smem in ONE batched phase:
// 15 independent float4 LDGs per thread -> single exposed DRAM latency.
// ---------------------------------------------------------------------------
template <int N>
__device__ __forceinline__ void level_smem(
    float* xk, float* xv, int baseNode, int lane,
    const float* __restrict__ Ws,
    const float* __restrict__ pb, const float* __restrict__ pth,
    const float* __restrict__ pta, const float* __restrict__ pvr)
{
#pragma unroll
    for (int l = 0; l < N; ++l) {
        const int node = baseNode + l;
        const float* __restrict__ wrow = Ws + node * 1056 + lane * 33;
        float ok = 0.f, ov = 0.f;
#pragma unroll
        for (int d = 0; d < 32; ++d) {
            const float ak = __shfl_sync(FULL_MASK, xk[l], d);
            const float av = __shfl_sync(FULL_MASK, xv[l], d);
            const float w  = wrow[d];
            ok = fmaf(ak, w, ok);
            ov = fmaf(av, w, ov);
        }
        const float bl = pb[node * 32 + lane];
        ok += bl;
        ov += bl;

        const float th = pth[node * 32 + lane];
        const float ta = pta[node * 32 + lane];
        const float vr = pvr[node * 32 + lane];
        const float sk = (xk[l] >= th) ? 1.f : 0.f;
        const float va = xk[l] * (1.f - sk) + vr * sk;
        const float v2 = fmaf(ta, va, xv[l]);
        const float sv = (v2 >= th) ? 1.f : 0.f;

        xk[l] = ok * sk;
        xv[l] = ov * sv;
    }
}

__global__ __launch_bounds__(256) void tree_kernel(
    const float* __restrict__ key_value,
    const float* __restrict__ W,
    const float* __restrict__ bvec,
    const float* __restrict__ thr,
    const float* __restrict__ tau,
    const float* __restrict__ vres)
{
    extern __shared__ float smem[];
    float* Ws  = smem;               // 15 * 1056 = 15840 floats
    float* pb  = smem + 15 * 1056;   // 480
    float* pth = pb  + 480;
    float* pta = pth + 480;
    float* pvr = pta + 480;

    const int tid  = threadIdx.x;
    const int lane = tid & 31;
    const int h    = tid >> 5;       // warp = head
    const int b    = blockIdx.x;     // block = batch

    // ---- batched prefetch: all W (3840 float4) + all params -----------------
    const float4* __restrict__ W4 = reinterpret_cast<const float4*>(W);
#pragma unroll
    for (int i = tid; i < 3840; i += 256) {
        const float4 w = W4[i];
        const int node = i >> 8;          // i / 256 (256 float4 per node)
        const int rem  = i & 255;
        const int o    = rem >> 3;        // 8 float4 per row
        const int d4   = (rem & 7) << 2;
        float* dst = &Ws[node * 1056 + o * 33 + d4];
        dst[0] = w.x; dst[1] = w.y; dst[2] = w.z; dst[3] = w.w;
    }
#pragma unroll
    for (int i = tid; i < 480; i += 256) {
        pb[i]  = bvec[i];
        pth[i] = thr[i];
        pta[i] = tau[i];
        pvr[i] = vres[i];
    }

    // leaf loads (independent of smem fill): leaf[m] = key_value[b, m, h*32+lane]
    float xk[8], xv[8];
#pragma unroll
    for (int m = 0; m < 8; ++m) {
        const float v = __ldg(&key_value[(b * 16 + m) * 256 + h * 32 + lane]);
        xk[m] = v;
        xv[m] = v;
    }

    __syncthreads();

    // Level 1: nodes 7..14 on 8 leaves
    level_smem<8>(xk, xv, 7, lane, Ws, pb, pth, pta, pvr);
#pragma unroll
    for (int l = 0; l < 4; ++l) {
        xk[l] = 0.5f * (xk[2 * l] + xk[2 * l + 1]);
        xv[l] = 0.5f * (xv[2 * l] + xv[2 * l + 1]);
    }
    level_smem<4>(xk, xv, 3, lane, Ws, pb, pth, pta, pvr);
#pragma unroll
    for (int l = 0; l < 2; ++l) {
        xk[l] = 0.5f * (xk[2 * l] + xk[2 * l + 1]);
        xv[l] = 0.5f * (xv[2 * l] + xv[2 * l + 1]);
    }
    level_smem<2>(xk, xv, 1, lane, Ws, pb, pth, pta, pvr);
    xk[0] = 0.5f * (xk[0] + xk[1]);
    xv[0] = 0.5f * (xv[0] + xv[1]);
    level_smem<1>(xk, xv, 0, lane, Ws, pb, pth, pta, pvr);

    // softmax over a single tree node == 1.0 -> attn_out = tree_v broadcast.
    g_tv[b * 256 + h * 32 + lane] = xv[0];
}

// ---------------------------------------------------------------------------
// Kernel B: fused residual-add + LayerNorm. One warp per TWO rows (D=256).
// Streaming hints: query read once (__ldcs), out written once (__stcs).
// 268 MB mandatory HBM traffic.
// ---------------------------------------------------------------------------
__global__ __launch_bounds__(256) void ln_kernel(
    const float* __restrict__ query,
    const float* __restrict__ gamma,
    const float* __restrict__ beta,
    float* __restrict__ out)
{
    const int  lane = threadIdx.x & 31;
    const long long warp = (long long)blockIdx.x * 8 + (threadIdx.x >> 5);
    const long long r0 = warp * 2;          // rows r0, r0+1 (same batch: boundary even)
    const int  b = (int)(r0 >> 13);

    const float4* __restrict__ q0r = reinterpret_cast<const float4*>(query) + r0 * 64;
    const float4* __restrict__ q1r = q0r + 64;
    const float4* __restrict__ tvr = reinterpret_cast<const float4*>(g_tv) + b * 64;
    const float4* __restrict__ g4  = reinterpret_cast<const float4*>(gamma);
    const float4* __restrict__ be4 = reinterpret_cast<const float4*>(beta);

    // 4 independent streaming row loads in flight
    const float4 qa0 = __ldcs(&q0r[lane]);
    const float4 qa1 = __ldcs(&q0r[lane + 32]);
    const float4 qb0 = __ldcs(&q1r[lane]);
    const float4 qb1 = __ldcs(&q1r[lane + 32]);
    const float4 t0  = tvr[lane];
    const float4 t1  = tvr[lane + 32];

    float4 xa0 = make_float4(qa0.x + t0.x, qa0.y + t0.y, qa0.z + t0.z, qa0.w + t0.w);
    float4 xa1 = make_float4(qa1.x + t1.x, qa1.y + t1.y, qa1.z + t1.z, qa1.w + t1.w);
    float4 xb0 = make_float4(qb0.x + t0.x, qb0.y + t0.y, qb0.z + t0.z, qb0.w + t0.w);
    float4 xb1 = make_float4(qb1.x + t1.x, qb1.y + t1.y, qb1.z + t1.z, qb1.w + t1.w);

    float sa  = xa0.x + xa0.y + xa0.z + xa0.w + xa1.x + xa1.y + xa1.z + xa1.w;
    float ssa = xa0.x*xa0.x + xa0.y*xa0.y + xa0.z*xa0.z + xa0.w*xa0.w
              + xa1.x*xa1.x + xa1.y*xa1.y + xa1.z*xa1.z + xa1.w*xa1.w;
    float sb  = xb0.x + xb0.y + xb0.z + xb0.w + xb1.x + xb1.y + xb1.z + xb1.w;
    float ssb = xb0.x*xb0.x + xb0.y*xb0.y + xb0.z*xb0.z + xb0.w*xb0.w
              + xb1.x*xb1.x + xb1.y*xb1.y + xb1.z*xb1.z + xb1.w*xb1.w;

#pragma unroll
    for (int off = 16; off > 0; off >>= 1) {
        sa  += __shfl_xor_sync(FULL_MASK, sa,  off);
        ssa += __shfl_xor_sync(FULL_MASK, ssa, off);
        sb  += __shfl_xor_sync(FULL_MASK, sb,  off);
        ssb += __shfl_xor_sync(FULL_MASK, ssb, off);
    }

    const float ma   = sa * (1.f / 256.f);
    const float inva = rsqrtf(ssa * (1.f / 256.f) - ma * ma + 1e-5f);
    const float mb   = sb * (1.f / 256.f);
    const float invb = rsqrtf(ssb * (1.f / 256.f) - mb * mb + 1e-5f);

    const float4 g0 = __ldg(&g4[lane]);
    const float4 g1 = __ldg(&g4[lane + 32]);
    const float4 b0 = __ldg(&be4[lane]);
    const float4 b1 = __ldg(&be4[lane + 32]);

    float4 ya0, ya1, yb0, yb1;
    ya0.x = fmaf((xa0.x - ma) * inva, g0.x, b0.x);
    ya0.y = fmaf((xa0.y - ma) * inva, g0.y, b0.y);
    ya0.z = fmaf((xa0.z - ma) * inva, g0.z, b0.z);
    ya0.w = fmaf((xa0.w - ma) * inva, g0.w, b0.w);
    ya1.x = fmaf((xa1.x - ma) * inva, g1.x, b1.x);
    ya1.y = fmaf((xa1.y - ma) * inva, g1.y, b1.y);
    ya1.z = fmaf((xa1.z - ma) * inva, g1.z, b1.z);
    ya1.w = fmaf((xa1.w - ma) * inva, g1.w, b1.w);
    yb0.x = fmaf((xb0.x - mb) * invb, g0.x, b0.x);
    yb0.y = fmaf((xb0.y - mb) * invb, g0.y, b0.y);
    yb0.z = fmaf((xb0.z - mb) * invb, g0.z, b0.z);
    yb0.w = fmaf((xb0.w - mb) * invb, g0.w, b0.w);
    yb1.x = fmaf((xb1.x - mb) * invb, g1.x, b1.x);
    yb1.y = fmaf((xb1.y - mb) * invb, g1.y, b1.y);
    yb1.z = fmaf((xb1.z - mb) * invb, g1.z, b1.z);
    yb1.w = fmaf((xb1.w - mb) * invb, g1.w, b1.w);

    float4* __restrict__ o0 = reinterpret_cast<float4*>(out) + r0 * 64;
    float4* __restrict__ o1 = o0 + 64;
    __stcs(&o0[lane],      ya0);
    __stcs(&o0[lane + 32], ya1);
    __stcs(&o1[lane],      yb0);
    __stcs(&o1[lane + 32], yb1);
}

// ---------------------------------------------------------------------------
// Inputs (metadata order): query, key_value, W, b, thr, tau, vres, gamma, beta
// Output: float32, 16*8192*256 elements
// ---------------------------------------------------------------------------
extern "C" void kernel_launch(void* const* d_in, const int* in_sizes, int n_in,
                              void* d_out, int out_size)
{
    (void)in_sizes; (void)n_in; (void)out_size;
    const float* query = (const float*)d_in[0];
    const float* kv    = (const float*)d_in[1];
    const float* W     = (const float*)d_in[2];
    const float* bvec  = (const float*)d_in[3];
    const float* thr   = (const float*)d_in[4];
    const float* tau   = (const float*)d_in[5];
    const float* vres  = (const float*)d_in[6];
    const float* gamma = (const float*)d_in[7];
    const float* beta  = (const float*)d_in[8];
    float* out = (float*)d_out;

    // 15*1056 W floats + 4*480 param floats = 17760 floats = 71040 bytes
    const int tree_smem = (15 * 1056 + 4 * 480) * (int)sizeof(float);
    static bool attr_set = false;
    if (!attr_set) {
        cudaFuncSetAttribute(tree_kernel,
                             cudaFuncAttributeMaxDynamicSharedMemorySize,
                             tree_smem);
        attr_set = true;
    }

    // Kernel A: one block per batch, 8 warps = 8 heads
    tree_kernel<<<16, 256, tree_smem>>>(kv, W, bvec, thr, tau, vres);

    // Kernel B: 131072 rows, 2 rows/warp, 8 warps/block -> 8192 blocks
    ln_kernel<<<8192, 256>>>(query, gamma, beta, out);
}

// round 4
// speedup vs baseline: 2.3280x; 1.0907x over previous
#include <cuda_runtime.h>

#define FULL_MASK 0xffffffffu

// Scratch for tree_v, laid out as [B=16][D=256] (head h occupies channels h*32..h*32+31)
__device__ float g_tv[16 * 256];

// ---------------------------------------------------------------------------
// Kernel A: LIF tree. One block per (batch, head): 128 blocks x 256 threads.
// Warp l owns node l of the current level (level1: 8 warps run 8 nodes
// concurrently). Each warp stages ONLY its node's W into a warp-private
// padded smem slot (stride-33 rows -> conflict-free LDS; __syncwarp only).
// Merges between levels go through a small smem buffer + __syncthreads.
// ---------------------------------------------------------------------------
__device__ __forceinline__ void node_step(
    float& xk, float& xv, int node, int lane,
    float* __restrict__ Wslot,
    const float* __restrict__ W,
    const float* __restrict__ bvec, const float* __restrict__ thr,
    const float* __restrict__ tau,  const float* __restrict__ vres)
{
    // stage W[node] (32x32) into Wslot with padding: 8 float4 per lane, coalesced
    const float4* __restrict__ Wn = reinterpret_cast<const float4*>(W + node * 1024);
#pragma unroll
    for (int i = lane; i < 256; i += 32) {
        const float4 w = Wn[i];
        const int o  = i >> 3;
        const int d4 = (i & 7) << 2;
        float* dst = &Wslot[o * 33 + d4];
        dst[0] = w.x; dst[1] = w.y; dst[2] = w.z; dst[3] = w.w;
    }
    __syncwarp();

    const float* __restrict__ wrow = Wslot + lane * 33;
    float ok = 0.f, ov = 0.f;
#pragma unroll
    for (int d = 0; d < 32; ++d) {
        const float ak = __shfl_sync(FULL_MASK, xk, d);
        const float av = __shfl_sync(FULL_MASK, xv, d);
        const float w  = wrow[d];
        ok = fmaf(ak, w, ok);
        ov = fmaf(av, w, ov);
    }
    const float bl = __ldg(&bvec[node * 32 + lane]);
    ok += bl;
    ov += bl;

    const float th = __ldg(&thr[node * 32 + lane]);
    const float ta = __ldg(&tau[node * 32 + lane]);
    const float vr = __ldg(&vres[node * 32 + lane]);
    const float sk = (xk >= th) ? 1.f : 0.f;
    const float va = xk * (1.f - sk) + vr * sk;
    const float v2 = fmaf(ta, va, xv);
    const float sv = (v2 >= th) ? 1.f : 0.f;

    xk = ok * sk;
    xv = ov * sv;
}

__global__ __launch_bounds__(256) void tree_kernel(
    const float* __restrict__ key_value,
    const float* __restrict__ W,
    const float* __restrict__ bvec,
    const float* __restrict__ thr,
    const float* __restrict__ tau,
    const float* __restrict__ vres)
{
    __shared__ float Wslots[8][1056];   // warp-private staging, 33792 B
    __shared__ float ks[8][32];
    __shared__ float vs[8][32];

    const int tid  = threadIdx.x;
    const int lane = tid & 31;
    const int w    = tid >> 5;          // warp id = node index within level
    const int b    = blockIdx.x >> 3;
    const int h    = blockIdx.x & 7;

    float* Wslot = Wslots[w];

    // leaf w: key_value[b, w, h*32 + lane]
    float xk = __ldg(&key_value[(b * 16 + w) * 256 + h * 32 + lane]);
    float xv = xk;

    // ---- level 1: 8 nodes (7..14), all warps active -------------------------
    node_step(xk, xv, 7 + w, lane, Wslot, W, bvec, thr, tau, vres);
    ks[w][lane] = xk; vs[w][lane] = xv;
    __syncthreads();

    // ---- level 2: 4 nodes (3..6) --------------------------------------------
    if (w < 4) {
        xk = 0.5f * (ks[2 * w][lane] + ks[2 * w + 1][lane]);
        xv = 0.5f * (vs[2 * w][lane] + vs[2 * w + 1][lane]);
        node_step(xk, xv, 3 + w, lane, Wslot, W, bvec, thr, tau, vres);
    }
    __syncthreads();
    if (w < 4) { ks[w][lane] = xk; vs[w][lane] = xv; }
    __syncthreads();

    // ---- level 3: 2 nodes (1..2) --------------------------------------------
    if (w < 2) {
        xk = 0.5f * (ks[2 * w][lane] + ks[2 * w + 1][lane]);
        xv = 0.5f * (vs[2 * w][lane] + vs[2 * w + 1][lane]);
        node_step(xk, xv, 1 + w, lane, Wslot, W, bvec, thr, tau, vres);
    }
    __syncthreads();
    if (w < 2) { ks[w][lane] = xk; vs[w][lane] = xv; }
    __syncthreads();

    // ---- level 4: root node 0 ------------------------------------------------
    if (w == 0) {
        xk = 0.5f * (ks[0][lane] + ks[1][lane]);
        xv = 0.5f * (vs[0][lane] + vs[1][lane]);
        node_step(xk, xv, 0, lane, Wslot, W, bvec, thr, tau, vres);
        // softmax over a single tree node == 1.0 -> attn_out = tree_v broadcast
        g_tv[b * 256 + h * 32 + lane] = xv;
    }
}

// ---------------------------------------------------------------------------
// Kernel B: fused residual-add + LayerNorm. One warp per FOUR rows (D=256):
// 8 independent LDG.128 in flight per warp. 268 MB mandatory HBM traffic.
// ---------------------------------------------------------------------------
__global__ __launch_bounds__(256) void ln_kernel(
    const float* __restrict__ query,
    const float* __restrict__ gamma,
    const float* __restrict__ beta,
    float* __restrict__ out)
{
    const int  lane = threadIdx.x & 31;
    const long long warp = (long long)blockIdx.x * 8 + (threadIdx.x >> 5);
    const long long r0 = warp * 4;           // rows r0..r0+3 (same batch)
    const int  b = (int)(r0 >> 13);

    const float4* __restrict__ qr  = reinterpret_cast<const float4*>(query) + r0 * 64;
    const float4* __restrict__ tvr = reinterpret_cast<const float4*>(g_tv) + b * 64;
    const float4* __restrict__ g4  = reinterpret_cast<const float4*>(gamma);
    const float4* __restrict__ be4 = reinterpret_cast<const float4*>(beta);

    // 8 independent streaming row loads in flight
    float4 q[4][2];
#pragma unroll
    for (int r = 0; r < 4; ++r) {
        q[r][0] = __ldcs(&qr[r * 64 + lane]);
        q[r][1] = __ldcs(&qr[r * 64 + lane + 32]);
    }
    const float4 t0 = tvr[lane];
    const float4 t1 = tvr[lane + 32];

    float s[4], ss[4];
#pragma unroll
    for (int r = 0; r < 4; ++r) {
        float4 x0 = make_float4(q[r][0].x + t0.x, q[r][0].y + t0.y,
                                q[r][0].z + t0.z, q[r][0].w + t0.w);
        float4 x1 = make_float4(q[r][1].x + t1.x, q[r][1].y + t1.y,
                                q[r][1].z + t1.z, q[r][1].w + t1.w);
        q[r][0] = x0; q[r][1] = x1;
        s[r]  = x0.x + x0.y + x0.z + x0.w + x1.x + x1.y + x1.z + x1.w;
        ss[r] = x0.x*x0.x + x0.y*x0.y + x0.z*x0.z + x0.w*x0.w
              + x1.x*x1.x + x1.y*x1.y + x1.z*x1.z + x1.w*x1.w;
    }

#pragma unroll
    for (int off = 16; off > 0; off >>= 1) {
#pragma unroll
        for (int r = 0; r < 4; ++r) {
            s[r]  += __shfl_xor_sync(FULL_MASK, s[r],  off);
            ss[r] += __shfl_xor_sync(FULL_MASK, ss[r], off);
        }
    }

    const float4 g0 = __ldg(&g4[lane]);
    const float4 g1 = __ldg(&g4[lane + 32]);
    const float4 b0 = __ldg(&be4[lane]);
    const float4 b1 = __ldg(&be4[lane + 32]);

    float4* __restrict__ o4 = reinterpret_cast<float4*>(out) + r0 * 64;
#pragma unroll
    for (int r = 0; r < 4; ++r) {
        const float m   = s[r] * (1.f / 256.f);
        const float inv = rsqrtf(ss[r] * (1.f / 256.f) - m * m + 1e-5f);
        float4 y0, y1;
        y0.x = fmaf((q[r][0].x - m) * inv, g0.x, b0.x);
        y0.y = fmaf((q[r][0].y - m) * inv, g0.y, b0.y);
        y0.z = fmaf((q[r][0].z - m) * inv, g0.z, b0.z);
        y0.w = fmaf((q[r][0].w - m) * inv, g0.w, b0.w);
        y1.x = fmaf((q[r][1].x - m) * inv, g1.x, b1.x);
        y1.y = fmaf((q[r][1].y - m) * inv, g1.y, b1.y);
        y1.z = fmaf((q[r][1].z - m) * inv, g1.z, b1.z);
        y1.w = fmaf((q[r][1].w - m) * inv, g1.w, b1.w);
        __stcs(&o4[r * 64 + lane],      y0);
        __stcs(&o4[r * 64 + lane + 32], y1);
    }
}

// ---------------------------------------------------------------------------
// Inputs (metadata order): query, key_value, W, b, thr, tau, vres, gamma, beta
// Output: float32, 16*8192*256 elements
// ---------------------------------------------------------------------------
extern "C" void kernel_launch(void* const* d_in, const int* in_sizes, int n_in,
                              void* d_out, int out_size)
{
    (void)in_sizes; (void)n_in; (void)out_size;
    const float* query = (const float*)d_in[0];
    const float* kv    = (const float*)d_in[1];
    const float* W     = (const float*)d_in[2];
    const float* bvec  = (const float*)d_in[3];
    const float* thr   = (const float*)d_in[4];
    const float* tau   = (const float*)d_in[5];
    const float* vres  = (const float*)d_in[6];
    const float* gamma = (const float*)d_in[7];
    const float* beta  = (const float*)d_in[8];
    float* out = (float*)d_out;

    // Kernel A: one block per (batch, head); warp = node within level
    tree_kernel<<<128, 256>>>(kv, W, bvec, thr, tau, vres);

    // Kernel B: 131072 rows, 4 rows/warp, 8 warps/block -> 4096 blocks
    ln_kernel<<<4096, 256>>>(query, gamma, beta, out);
}